// round 10
// baseline (speedup 1.0000x reference)
#include <cuda_runtime.h>

#define DMODEL     1024
#define NEXP       8
#define TOKENS_TOT 32768
#define TPB        128
#define WARPS      4            // per CTA
#define TPW        16           // tokens per warp
#define TPG        4            // tokens per group (inner batch)
#define NGRP       (TPW / TPG)  // 4
#define NBLOCKS    (TOKENS_TOT / (WARPS * TPW))   // 512

typedef unsigned long long ull;

// ---------- packed fp32x2 helpers (sm_103a FFMA2 path) ----------
__device__ __forceinline__ ull pack2(float lo, float hi) {
    ull d;
    asm("mov.b64 %0, {%1, %2};" : "=l"(d) : "f"(lo), "f"(hi));
    return d;
}
__device__ __forceinline__ void unpack2(ull v, float& lo, float& hi) {
    asm("mov.b64 {%0, %1}, %2;" : "=f"(lo), "=f"(hi) : "l"(v));
}
__device__ __forceinline__ ull ffma2(ull a, ull b, ull c) {
    ull d;
    asm("fma.rn.f32x2 %0, %1, %2, %3;" : "=l"(d) : "l"(a), "l"(b), "l"(c));
    return d;
}

// ---------- integer warp redux (f32 redux does NOT exist on sm_103) ----------
__device__ __forceinline__ unsigned redux_max_u32(unsigned v) {
    unsigned r;
    asm volatile("redux.sync.max.u32 %0, %1, 0xffffffff;" : "=r"(r) : "r"(v));
    return r;
}
__device__ __forceinline__ unsigned redux_min_u32(unsigned v) {
    unsigned r;
    asm volatile("redux.sync.min.u32 %0, %1, 0xffffffff;" : "=r"(r) : "r"(v));
    return r;
}

// Order-preserving float <-> u32 total-order map: u32 max == float max.
__device__ __forceinline__ unsigned fmono(float v) {
    unsigned u = __float_as_uint(v);
    return ((int)u < 0) ? ~u : (u ^ 0x80000000u);
}
__device__ __forceinline__ float fmono_inv(unsigned k) {
    return __uint_as_float(((int)k < 0) ? (k ^ 0x80000000u) : ~k);
}

// Warp-autonomous gating: lane owns dims {c*128 + lane*4 .. +4 | c=0..7} so a
// single warp spans all 1024 dims of a token. W staged once in SMEM (32 KB),
// re-read per chunk amortized over 4 tokens. Per group of 4 tokens:
// 8 chunks x (4 LDG.128 + 8 LDS.128 + 64 FFMA2), then per token an in-warp
// 9-shfl butterfly (full logit) + redux top-2 epilogue. ZERO block barriers
// after staging.
__global__ void __launch_bounds__(TPB, 4)
gating_kernel(const float* __restrict__ x, const float* __restrict__ W,
              const float* __restrict__ b, float* __restrict__ out_w,
              float* __restrict__ out_i, int write_idx)
{
    __shared__ float4 Ws[NEXP * 256];   // 8 x 1024 floats = 32 KB

    const int tid  = threadIdx.x;
    const int lane = tid & 31;
    const int wid  = tid >> 5;

    // Stage W: 2048 float4 / 128 threads = 16 each.
    {
        const float4* Wv = (const float4*)W;
#pragma unroll
        for (int i = 0; i < 16; i++)
            Ws[tid + i * TPB] = Wv[tid + i * TPB];
    }
    __syncthreads();   // the only block barrier in the kernel

    const int   elane = (lane >> 2) & 7;      // expert this lane ends up with
    const float bval  = b[elane];

    const int t0 = (blockIdx.x * WARPS + wid) * TPW;
    const float4* xp4 = (const float4*)x + (size_t)t0 * 256 + lane;
    // token (g*4+t), chunk c lives at xp4[(g*4+t)*256 + c*32]

    // Prologue: load group 0, chunk 0 for 4 tokens.
    float4 xn0 = xp4[0 * 256];
    float4 xn1 = xp4[1 * 256];
    float4 xn2 = xp4[2 * 256];
    float4 xn3 = xp4[3 * 256];

#pragma unroll 1
    for (int g = 0; g < NGRP; g++) {
        ull acc[NEXP][TPG];
#pragma unroll
        for (int e = 0; e < NEXP; e++)
#pragma unroll
            for (int t = 0; t < TPG; t++) acc[e][t] = 0ull;

        const int gbase = g * TPG * 256;

#pragma unroll
        for (int c = 0; c < 8; c++) {
            // Consume prefetched x into packed form (this is the stall point).
            ull xlo[TPG], xhi[TPG];
            xlo[0] = pack2(xn0.x, xn0.y); xhi[0] = pack2(xn0.z, xn0.w);
            xlo[1] = pack2(xn1.x, xn1.y); xhi[1] = pack2(xn1.z, xn1.w);
            xlo[2] = pack2(xn2.x, xn2.y); xhi[2] = pack2(xn2.z, xn2.w);
            xlo[3] = pack2(xn3.x, xn3.y); xhi[3] = pack2(xn3.z, xn3.w);

            // Prefetch next chunk (or next group's chunk 0).
            if (c < 7) {
                const int o = gbase + (c + 1) * 32;
                xn0 = xp4[o + 0 * 256]; xn1 = xp4[o + 1 * 256];
                xn2 = xp4[o + 2 * 256]; xn3 = xp4[o + 3 * 256];
            } else if (g < NGRP - 1) {
                const int o = (g + 1) * TPG * 256;
                xn0 = xp4[o + 0 * 256]; xn1 = xp4[o + 1 * 256];
                xn2 = xp4[o + 2 * 256]; xn3 = xp4[o + 3 * 256];
            }

            // W for this chunk, 4 experts at a time (keeps W regs transient).
            const int wbase = c * 32 + lane;
#pragma unroll
            for (int eb = 0; eb < NEXP; eb += 4) {
                float4 w0 = Ws[(eb + 0) * 256 + wbase];
                float4 w1 = Ws[(eb + 1) * 256 + wbase];
                float4 w2 = Ws[(eb + 2) * 256 + wbase];
                float4 w3 = Ws[(eb + 3) * 256 + wbase];
                ull wl0 = pack2(w0.x, w0.y), wh0 = pack2(w0.z, w0.w);
                ull wl1 = pack2(w1.x, w1.y), wh1 = pack2(w1.z, w1.w);
                ull wl2 = pack2(w2.x, w2.y), wh2 = pack2(w2.z, w2.w);
                ull wl3 = pack2(w3.x, w3.y), wh3 = pack2(w3.z, w3.w);
#pragma unroll
                for (int t = 0; t < TPG; t++) {
                    acc[eb + 0][t] = ffma2(xhi[t], wh0, ffma2(xlo[t], wl0, acc[eb + 0][t]));
                    acc[eb + 1][t] = ffma2(xhi[t], wh1, ffma2(xlo[t], wl1, acc[eb + 1][t]));
                    acc[eb + 2][t] = ffma2(xhi[t], wh2, ffma2(xlo[t], wl2, acc[eb + 2][t]));
                    acc[eb + 3][t] = ffma2(xhi[t], wh3, ffma2(xlo[t], wl3, acc[eb + 3][t]));
                }
            }
        }

        // Finalize + epilogue per token, fully in-warp.
#pragma unroll
        for (int t = 0; t < TPG; t++) {
            float s[NEXP];
#pragma unroll
            for (int e = 0; e < NEXP; e++) {
                float lo, hi; unpack2(acc[e][t], lo, hi);
                s[e] = lo + hi;
            }

            // 9-shfl butterfly: experts over lane bits 4,3,2; dims over 1,0.
            const bool h16 = (lane & 16) != 0;
#pragma unroll
            for (int v = 0; v < 4; v++) {
                float d = __shfl_xor_sync(~0u, h16 ? s[v] : s[v + 4], 16);
                s[v] = (h16 ? s[v + 4] : s[v]) + d;
            }
            const bool h8 = (lane & 8) != 0;
#pragma unroll
            for (int v = 0; v < 2; v++) {
                float d = __shfl_xor_sync(~0u, h8 ? s[v] : s[v + 2], 8);
                s[v] = (h8 ? s[v + 2] : s[v]) + d;
            }
            const bool h4 = (lane & 4) != 0;
            {
                float d = __shfl_xor_sync(~0u, h4 ? s[0] : s[1], 4);
                s[0] = (h4 ? s[1] : s[0]) + d;
            }
            float r = s[0];
            r += __shfl_xor_sync(~0u, r, 2);
            r += __shfl_xor_sync(~0u, r, 1);

            // Lane now holds the complete logit for expert `elane` (x4 copies).
            const float L = r + bval;
            const unsigned key = fmono(L);
            unsigned k1 = redux_max_u32(key);
            unsigned i1 = redux_min_u32((key == k1) ? (unsigned)elane : 0xFFu);
            unsigned key2 = ((unsigned)elane == i1) ? 0u : key;
            unsigned k2 = redux_max_u32(key2);
            unsigned i2 = redux_min_u32((key2 == k2) ? (unsigned)elane : 0xFFu);

            const float m1 = fmono_inv(k1);
            const float m2 = fmono_inv(k2);
            const float tt  = __expf(m2 - m1);     // m2 <= m1 -> (0,1]
            const float inv = 1.0f / (1.0f + tt);

            const int token = t0 + g * TPG + t;
            if ((lane & 3) == 0) {
                float wgt = ((unsigned)elane == i1) ? inv
                          : (((unsigned)elane == i2) ? tt * inv : 0.0f);
                out_w[token * 8 + elane] = wgt;
            }
            if (lane == t * 8 && write_idx)
                *(float2*)(out_i + token * 2) =
                    make_float2((float)i1, (float)i2);
        }
    }
}

extern "C" void kernel_launch(void* const* d_in, const int* in_sizes, int n_in,
                              void* d_out, int out_size)
{
    const float* x = nullptr; const float* W = nullptr; const float* b = nullptr;
    for (int i = 0; i < n_in; i++) {
        if (in_sizes[i] == NEXP)                b = (const float*)d_in[i];
        else if (in_sizes[i] == NEXP * DMODEL)  W = (const float*)d_in[i];
        else                                    x = (const float*)d_in[i];
    }

    float* ow = (float*)d_out;                       // weights: [B,S,E] f32
    float* oi = ow + (size_t)TOKENS_TOT * NEXP;      // indices (as f32): [B,S,2]
    const int need = TOKENS_TOT * NEXP + TOKENS_TOT * 2;
    const int write_idx = (out_size >= need) ? 1 : 0;

    gating_kernel<<<NBLOCKS, TPB>>>(x, W, b, ow, oi, write_idx);
}